// round 10
// baseline (speedup 1.0000x reference)
#include <cuda_runtime.h>
#include <math.h>

#define NN 8192
#define EE 262144
#define CC 64
#define NMASK (NN - 1)
#define ELLW 96
#define HBITS 20
#define HSIZE (1 << HBITS)
#define HMASK (HSIZE - 1)
#define WP 68   // padded W column stride (16B aligned, conflict-free LDS.128)

typedef unsigned long long u64;

// ---- static device scratch (zero-initialized at module load) ----
__device__ u64   g_hash[HSIZE];            // 8 MB open-addressed LWW table (L2-resident)
__device__ int   g_slotrec[EE];            // slot touched by each edge (for clean)
__device__ int   g_rowcnt[NN];
__device__ float g_deg[NN];                // accumulated edge weight (identity added in prep)
__device__ float g_dinv[NN];
__device__ u64   g_ell[NN * ELLW];         // packed (w_bits<<32 | col); row stride 768B
__device__ float g_z[NN * CC];             // dinv * x
__device__ float g_tx1[NN * CC];
__device__ float g_zt[NN * CC];            // dinv * tx1
__device__ float g_tx2[NN * CC];

__device__ __forceinline__ void add_entry(int r, int c, float w) {
    int pos = atomicAdd(&g_rowcnt[r], 1);
    if (pos < ELLW) {
        u64 pk = ((u64)__float_as_uint(w) << 32) | (u64)(unsigned)c;
        g_ell[r * ELLW + pos] = pk;
    }
    atomicAdd(&g_deg[r], w);
}

// ---- K1: single-pass dedup + ELL build via L2-resident hash ----
__global__ void k_build(const int* __restrict__ ei, const float* __restrict__ ew,
                        const float* __restrict__ adaptive) {
    int e = blockIdx.x * blockDim.x + threadIdx.x;
    if (e >= EE) return;
    float sig = 1.0f / (1.0f + expf(-adaptive[0]));
    int r = ei[e] & NMASK;
    int c = ei[EE + e] & NMASK;
    unsigned key = (unsigned)(r * NN + c);          // < 2^26
    u64 desired = ((u64)(key + 1) << 32) | (u64)(unsigned)(e + 1);
    unsigned slot = (key * 2654435761u) >> (32 - HBITS);
    float aw = ew[e] * sig;
    while (true) {
        u64 old = atomicCAS(&g_hash[slot], 0ULL, desired);
        if (old == 0ULL) {
            add_entry(r, c, aw);
            g_slotrec[e] = (int)slot;
            break;
        }
        if ((unsigned)(old >> 32) == key + 1) {
            if ((unsigned)old < (unsigned)(e + 1)) {
                u64 prev = atomicMax(&g_hash[slot], desired);
                if ((unsigned)prev < (unsigned)(e + 1)) {
                    int eprev = (int)(unsigned)prev - 1;
                    add_entry(r, c, aw);
                    add_entry(r, c, -(ew[eprev] * sig));
                }
            }
            g_slotrec[e] = (int)slot;
            break;
        }
        slot = (slot + 1) & HMASK;
    }
}

// ---- K2: dinv = (1+deg)^-1/2 ; z = dinv*x ----
__global__ void k_prep(const float* __restrict__ x) {
    int i = blockIdx.x * blockDim.x + threadIdx.x;
    if (i >= NN * 32) return;
    int row = i >> 5;
    float di = rsqrtf(1.0f + g_deg[row]);
    float2 v = ((const float2*)x)[i];
    v.x *= di; v.y *= di;
    ((float2*)g_z)[i] = v;
    if ((i & 31) == 0) g_dinv[row] = di;
}

// ---- shared SpMM row body: MLP-8 gather, ELL via 4x LDG.128 (R8-proven) ----
__device__ __forceinline__ float2 gather_row(const float2* __restrict__ z2,
                                             int row, int t) {
    float2 acc = z2[row * 32 + t];          // identity term (dinv*xin[row])
    int cnt = g_rowcnt[row]; if (cnt > ELLW) cnt = ELLW;
    const ulonglong2* ell2 = (const ulonglong2*)&g_ell[row * ELLW];
    int k = 0;
    for (; k + 8 <= cnt; k += 8) {
        ulonglong2 q0 = __ldg(&ell2[(k >> 1)]);
        ulonglong2 q1 = __ldg(&ell2[(k >> 1) + 1]);
        ulonglong2 q2 = __ldg(&ell2[(k >> 1) + 2]);
        ulonglong2 q3 = __ldg(&ell2[(k >> 1) + 3]);
        float2 c0 = z2[(int)(q0.x & 0xffffffffu) * 32 + t];
        float2 c1 = z2[(int)(q0.y & 0xffffffffu) * 32 + t];
        float2 c2 = z2[(int)(q1.x & 0xffffffffu) * 32 + t];
        float2 c3 = z2[(int)(q1.y & 0xffffffffu) * 32 + t];
        float2 c4 = z2[(int)(q2.x & 0xffffffffu) * 32 + t];
        float2 c5 = z2[(int)(q2.y & 0xffffffffu) * 32 + t];
        float2 c6 = z2[(int)(q3.x & 0xffffffffu) * 32 + t];
        float2 c7 = z2[(int)(q3.y & 0xffffffffu) * 32 + t];
        float w0 = __uint_as_float((unsigned)(q0.x >> 32));
        float w1 = __uint_as_float((unsigned)(q0.y >> 32));
        float w2 = __uint_as_float((unsigned)(q1.x >> 32));
        float w3 = __uint_as_float((unsigned)(q1.y >> 32));
        float w4 = __uint_as_float((unsigned)(q2.x >> 32));
        float w5 = __uint_as_float((unsigned)(q2.y >> 32));
        float w6 = __uint_as_float((unsigned)(q3.x >> 32));
        float w7 = __uint_as_float((unsigned)(q3.y >> 32));
        acc.x += w0 * c0.x; acc.y += w0 * c0.y;
        acc.x += w1 * c1.x; acc.y += w1 * c1.y;
        acc.x += w2 * c2.x; acc.y += w2 * c2.y;
        acc.x += w3 * c3.x; acc.y += w3 * c3.y;
        acc.x += w4 * c4.x; acc.y += w4 * c4.y;
        acc.x += w5 * c5.x; acc.y += w5 * c5.y;
        acc.x += w6 * c6.x; acc.y += w6 * c6.y;
        acc.x += w7 * c7.x; acc.y += w7 * c7.y;
    }
    for (; k < cnt; k++) {
        u64 pk = __ldg(&g_ell[row * ELLW + k]);
        float2 zc = z2[(int)(pk & 0xffffffffu) * 32 + t];
        float w = __uint_as_float((unsigned)(pk >> 32));
        acc.x += w * zc.x; acc.y += w * zc.y;
    }
    return acc;
}

// ---- K3: tx1 = L @ x ; zt = dinv*tx1 ----
__global__ void __launch_bounds__(256, 8) k_spmm1(const float* __restrict__ x) {
    int row = blockIdx.x * 8 + threadIdx.y;
    int t = threadIdx.x;
    float2 acc = gather_row((const float2*)g_z, row, t);
    float di = g_dinv[row];
    float2 xr = ((const float2*)x)[row * 32 + t];
    float2 y; y.x = xr.x - di * acc.x; y.y = xr.y - di * acc.y;
    ((float2*)g_tx1)[row * 32 + t] = y;
    float2 zt; zt.x = di * y.x; zt.y = di * y.y;
    ((float2*)g_zt)[row * 32 + t] = zt;
}

// ---- K4: tx2 = 2*(L @ tx1) - x ----
__global__ void __launch_bounds__(256, 8) k_spmm2(const float* __restrict__ x) {
    int row = blockIdx.x * 8 + threadIdx.y;
    int t = threadIdx.x;
    float2 acc = gather_row((const float2*)g_zt, row, t);
    float di = g_dinv[row];
    float2 x1 = ((const float2*)g_tx1)[row * 32 + t];
    float2 x0 = ((const float2*)x)[row * 32 + t];
    float2 y;
    y.x = 2.0f * (x1.x - di * acc.x) - x0.x;
    y.y = 2.0f * (x1.y - di * acc.y) - x0.y;
    ((float2*)g_tx2)[row * 32 + t] = y;
}

// ---- K5: out = x@W0 + tx1@W1 + tx2@W2 + bias, plus fused scratch clean ----
extern __shared__ float s_dyn[];
__global__ void __launch_bounds__(256) k_gemm(const float* __restrict__ x,
                                              const float* __restrict__ W,
                                              const float* __restrict__ bias,
                                              float* __restrict__ out) {
    float* sWt = s_dyn;                     // 3 * 64 * WP floats ~= 51 KB
    int o = threadIdx.x;                    // 0..63 out channel
    int ty = threadIdx.y;                   // 0..3
    int tid = ty * 64 + o;
    for (int i = tid; i < 3 * CC * CC; i += 256) {
        int m = i >> 12;
        int rem = i & 4095;
        int c = rem >> 6, oo = rem & 63;
        sWt[(m * CC + oo) * WP + c] = W[i];
    }
    __syncthreads();

    const float* w0 = &sWt[(0 * CC + o) * WP];
    const float* w1 = &sWt[(1 * CC + o) * WP];
    const float* w2 = &sWt[(2 * CC + o) * WP];
    int rbase = blockIdx.x * 32;
    float b = bias[o];
#pragma unroll
    for (int j = 0; j < 8; j++) {
        int row = rbase + j * 4 + ty;
        const float4* x4  = (const float4*)(x + row * CC);
        const float4* t14 = (const float4*)(g_tx1 + row * CC);
        const float4* t24 = (const float4*)(g_tx2 + row * CC);
        float a = b;
#pragma unroll
        for (int c4 = 0; c4 < 16; c4++) {
            float4 v0 = __ldg(&x4[c4]);
            float4 v1 = __ldg(&t14[c4]);
            float4 v2 = __ldg(&t24[c4]);
            float4 u0 = *(const float4*)&w0[c4 * 4];
            float4 u1 = *(const float4*)&w1[c4 * 4];
            float4 u2 = *(const float4*)&w2[c4 * 4];
            a += v0.x * u0.x + v0.y * u0.y + v0.z * u0.z + v0.w * u0.w;
            a += v1.x * u1.x + v1.y * u1.y + v1.z * u1.z + v1.w * u1.w;
            a += v2.x * u2.x + v2.y * u2.y + v2.z * u2.z + v2.w * u2.w;
        }
        out[row * CC + o] = a;
    }

    // fused clean for next replay (gemm reads none of these)
    int g = blockIdx.x * 256 + tid;          // 65536 threads total
#pragma unroll
    for (int j = 0; j < 4; j++) g_hash[g_slotrec[g + j * 65536]] = 0ULL;
    if (g < NN) { g_deg[g] = 0.0f; g_rowcnt[g] = 0; }
}

extern "C" void kernel_launch(void* const* d_in, const int* in_sizes, int n_in,
                              void* d_out, int out_size) {
    const float* x        = (const float*)d_in[0];
    const int*   ei       = (const int*)d_in[1];
    const float* ew       = (const float*)d_in[2];
    const float* W        = (const float*)d_in[3];
    const float* adaptive = (const float*)d_in[4];
    const float* bias     = (const float*)d_in[5];
    float* out = (float*)d_out;

    const int gemm_smem = 3 * CC * WP * sizeof(float);   // ~51 KB
    cudaFuncSetAttribute(k_gemm, cudaFuncAttributeMaxDynamicSharedMemorySize, gemm_smem);

    k_build<<<EE / 256, 256>>>(ei, ew, adaptive);
    k_prep<<<(NN * 32) / 256, 256>>>(x);
    k_spmm1<<<NN / 8, dim3(32, 8)>>>(x);
    k_spmm2<<<NN / 8, dim3(32, 8)>>>(x);
    k_gemm<<<NN / 32, dim3(64, 4), gemm_smem>>>(x, W, bias, out);
}

// round 12
// speedup vs baseline: 1.3456x; 1.3456x over previous
#include <cuda_runtime.h>
#include <math.h>

#define NN 8192
#define EE 262144
#define CC 64
#define NMASK (NN - 1)
#define ELLW 96
#define HBITS 20
#define HSIZE (1 << HBITS)
#define HMASK (HSIZE - 1)
#define WP 68   // padded W column stride (16B aligned, conflict-free LDS.128)

typedef unsigned long long u64;

// ---- static device scratch (zero-initialized at module load) ----
__device__ u64   g_hash[HSIZE];            // 8 MB open-addressed LWW table (L2-resident)
__device__ int   g_slotrec[EE];            // slot touched by each edge (for clean)
__device__ int   g_rowcnt[NN];
__device__ float g_deg[NN];                // accumulated edge weight (identity added in prep)
__device__ float g_dinv[NN];
__device__ u64   g_ell[NN * ELLW];         // packed (w_bits<<32 | col); row stride 768B
__device__ float g_z[NN * CC];             // dinv * x
__device__ float g_tx1[NN * CC];
__device__ float g_zt[NN * CC];            // dinv * tx1
__device__ float g_tx2[NN * CC];

__device__ __forceinline__ void add_entry(int r, int c, float w) {
    int pos = atomicAdd(&g_rowcnt[r], 1);
    if (pos < ELLW) {
        u64 pk = ((u64)__float_as_uint(w) << 32) | (u64)(unsigned)c;
        g_ell[r * ELLW + pos] = pk;
    }
    atomicAdd(&g_deg[r], w);
}

// ---- K1: single-pass dedup + ELL build via L2-resident hash ----
__global__ void k_build(const int* __restrict__ ei, const float* __restrict__ ew,
                        const float* __restrict__ adaptive) {
    int e = blockIdx.x * blockDim.x + threadIdx.x;
    if (e >= EE) return;
    float sig = 1.0f / (1.0f + expf(-adaptive[0]));
    int r = ei[e] & NMASK;
    int c = ei[EE + e] & NMASK;
    unsigned key = (unsigned)(r * NN + c);          // < 2^26
    u64 desired = ((u64)(key + 1) << 32) | (u64)(unsigned)(e + 1);
    unsigned slot = (key * 2654435761u) >> (32 - HBITS);
    float aw = ew[e] * sig;
    while (true) {
        u64 old = atomicCAS(&g_hash[slot], 0ULL, desired);
        if (old == 0ULL) {
            add_entry(r, c, aw);
            g_slotrec[e] = (int)slot;
            break;
        }
        if ((unsigned)(old >> 32) == key + 1) {
            if ((unsigned)old < (unsigned)(e + 1)) {
                u64 prev = atomicMax(&g_hash[slot], desired);
                if ((unsigned)prev < (unsigned)(e + 1)) {
                    int eprev = (int)(unsigned)prev - 1;
                    add_entry(r, c, aw);
                    add_entry(r, c, -(ew[eprev] * sig));
                }
            }
            g_slotrec[e] = (int)slot;
            break;
        }
        slot = (slot + 1) & HMASK;
    }
}

// ---- K2: dinv = (1+deg)^-1/2 ; z = dinv*x ----
__global__ void k_prep(const float* __restrict__ x) {
    int i = blockIdx.x * blockDim.x + threadIdx.x;
    if (i >= NN * 32) return;
    int row = i >> 5;
    float di = rsqrtf(1.0f + g_deg[row]);
    float2 v = ((const float2*)x)[i];
    v.x *= di; v.y *= di;
    ((float2*)g_z)[i] = v;
    if ((i & 31) == 0) g_dinv[row] = di;
}

// ---- shared SpMM row body: MLP-8 gather, ELL via 4x LDG.128 ----
__device__ __forceinline__ float2 gather_row(const float2* __restrict__ z2,
                                             int row, int t) {
    float2 acc = z2[row * 32 + t];          // identity term (dinv*xin[row])
    int cnt = g_rowcnt[row]; if (cnt > ELLW) cnt = ELLW;
    const ulonglong2* ell2 = (const ulonglong2*)&g_ell[row * ELLW];
    int k = 0;
    for (; k + 8 <= cnt; k += 8) {
        ulonglong2 q0 = __ldg(&ell2[(k >> 1)]);
        ulonglong2 q1 = __ldg(&ell2[(k >> 1) + 1]);
        ulonglong2 q2 = __ldg(&ell2[(k >> 1) + 2]);
        ulonglong2 q3 = __ldg(&ell2[(k >> 1) + 3]);
        float2 c0 = z2[(int)(q0.x & 0xffffffffu) * 32 + t];
        float2 c1 = z2[(int)(q0.y & 0xffffffffu) * 32 + t];
        float2 c2 = z2[(int)(q1.x & 0xffffffffu) * 32 + t];
        float2 c3 = z2[(int)(q1.y & 0xffffffffu) * 32 + t];
        float2 c4 = z2[(int)(q2.x & 0xffffffffu) * 32 + t];
        float2 c5 = z2[(int)(q2.y & 0xffffffffu) * 32 + t];
        float2 c6 = z2[(int)(q3.x & 0xffffffffu) * 32 + t];
        float2 c7 = z2[(int)(q3.y & 0xffffffffu) * 32 + t];
        float w0 = __uint_as_float((unsigned)(q0.x >> 32));
        float w1 = __uint_as_float((unsigned)(q0.y >> 32));
        float w2 = __uint_as_float((unsigned)(q1.x >> 32));
        float w3 = __uint_as_float((unsigned)(q1.y >> 32));
        float w4 = __uint_as_float((unsigned)(q2.x >> 32));
        float w5 = __uint_as_float((unsigned)(q2.y >> 32));
        float w6 = __uint_as_float((unsigned)(q3.x >> 32));
        float w7 = __uint_as_float((unsigned)(q3.y >> 32));
        acc.x += w0 * c0.x; acc.y += w0 * c0.y;
        acc.x += w1 * c1.x; acc.y += w1 * c1.y;
        acc.x += w2 * c2.x; acc.y += w2 * c2.y;
        acc.x += w3 * c3.x; acc.y += w3 * c3.y;
        acc.x += w4 * c4.x; acc.y += w4 * c4.y;
        acc.x += w5 * c5.x; acc.y += w5 * c5.y;
        acc.x += w6 * c6.x; acc.y += w6 * c6.y;
        acc.x += w7 * c7.x; acc.y += w7 * c7.y;
    }
    for (; k < cnt; k++) {
        u64 pk = __ldg(&g_ell[row * ELLW + k]);
        float2 zc = z2[(int)(pk & 0xffffffffu) * 32 + t];
        float w = __uint_as_float((unsigned)(pk >> 32));
        acc.x += w * zc.x; acc.y += w * zc.y;
    }
    return acc;
}

// ---- K3: tx1 = L @ x ; zt = dinv*tx1 ----
__global__ void __launch_bounds__(256) k_spmm1(const float* __restrict__ x) {
    int row = blockIdx.x * 8 + threadIdx.y;
    int t = threadIdx.x;
    float2 acc = gather_row((const float2*)g_z, row, t);
    float di = g_dinv[row];
    float2 xr = ((const float2*)x)[row * 32 + t];
    float2 y; y.x = xr.x - di * acc.x; y.y = xr.y - di * acc.y;
    ((float2*)g_tx1)[row * 32 + t] = y;
    float2 zt; zt.x = di * y.x; zt.y = di * y.y;
    ((float2*)g_zt)[row * 32 + t] = zt;
}

// ---- K4: tx2 = 2*(L @ tx1) - x ----
__global__ void __launch_bounds__(256) k_spmm2(const float* __restrict__ x) {
    int row = blockIdx.x * 8 + threadIdx.y;
    int t = threadIdx.x;
    float2 acc = gather_row((const float2*)g_zt, row, t);
    float di = g_dinv[row];
    float2 x1 = ((const float2*)g_tx1)[row * 32 + t];
    float2 x0 = ((const float2*)x)[row * 32 + t];
    float2 y;
    y.x = 2.0f * (x1.x - di * acc.x) - x0.x;
    y.y = 2.0f * (x1.y - di * acc.y) - x0.y;
    ((float2*)g_tx2)[row * 32 + t] = y;
}

// ---- K5: out = x@W0 + tx1@W1 + tx2@W2 + bias ----
// W transposed in smem: sWt[m][o*WP + c], WP=68 -> 16B aligned rows,
// lanes o hit banks (4o+c)%32 within an 8-lane phase: conflict-free LDS.128.
extern __shared__ float s_dyn[];
__global__ void __launch_bounds__(256) k_gemm(const float* __restrict__ x,
                                              const float* __restrict__ W,
                                              const float* __restrict__ bias,
                                              float* __restrict__ out) {
    float* sWt = s_dyn;                     // 3 * 64 * WP floats ~= 51 KB
    int o = threadIdx.x;                    // 0..63 out channel
    int ty = threadIdx.y;                   // 0..3
    int tid = ty * 64 + o;
    for (int i = tid; i < 3 * CC * CC; i += 256) {
        int m = i >> 12;                    // /4096
        int rem = i & 4095;
        int c = rem >> 6, oo = rem & 63;
        sWt[(m * CC + oo) * WP + c] = W[i];
    }
    __syncthreads();

    const float* w0 = &sWt[(0 * CC + o) * WP];
    const float* w1 = &sWt[(1 * CC + o) * WP];
    const float* w2 = &sWt[(2 * CC + o) * WP];
    int rbase = blockIdx.x * 32;
    float b = bias[o];
#pragma unroll
    for (int j = 0; j < 8; j++) {
        int row = rbase + j * 4 + ty;
        const float4* x4  = (const float4*)(x + row * CC);
        const float4* t14 = (const float4*)(g_tx1 + row * CC);
        const float4* t24 = (const float4*)(g_tx2 + row * CC);
        float a = b;
#pragma unroll
        for (int c4 = 0; c4 < 16; c4++) {
            float4 v0 = __ldg(&x4[c4]);
            float4 v1 = __ldg(&t14[c4]);
            float4 v2 = __ldg(&t24[c4]);
            float4 u0 = *(const float4*)&w0[c4 * 4];
            float4 u1 = *(const float4*)&w1[c4 * 4];
            float4 u2 = *(const float4*)&w2[c4 * 4];
            a += v0.x * u0.x + v0.y * u0.y + v0.z * u0.z + v0.w * u0.w;
            a += v1.x * u1.x + v1.y * u1.y + v1.z * u1.z + v1.w * u1.w;
            a += v2.x * u2.x + v2.y * u2.y + v2.z * u2.z + v2.w * u2.w;
        }
        out[row * CC + o] = a;
    }
}

// ---- K6: clean touched hash slots + per-row counters for next replay ----
__global__ void k_clean() {
    int i = blockIdx.x * blockDim.x + threadIdx.x;
    if (i < NN) { g_deg[i] = 0.0f; g_rowcnt[i] = 0; }
    if (i < EE) g_hash[g_slotrec[i]] = 0ULL;
}

extern "C" void kernel_launch(void* const* d_in, const int* in_sizes, int n_in,
                              void* d_out, int out_size) {
    const float* x        = (const float*)d_in[0];
    const int*   ei       = (const int*)d_in[1];
    const float* ew       = (const float*)d_in[2];
    const float* W        = (const float*)d_in[3];
    const float* adaptive = (const float*)d_in[4];
    const float* bias     = (const float*)d_in[5];
    float* out = (float*)d_out;

    const int gemm_smem = 3 * CC * WP * sizeof(float);   // ~51 KB
    cudaFuncSetAttribute(k_gemm, cudaFuncAttributeMaxDynamicSharedMemorySize, gemm_smem);

    k_build<<<EE / 256, 256>>>(ei, ew, adaptive);
    k_prep<<<(NN * 32) / 256, 256>>>(x);
    k_spmm1<<<NN / 8, dim3(32, 8)>>>(x);
    k_spmm2<<<NN / 8, dim3(32, 8)>>>(x);
    k_gemm<<<NN / 32, dim3(64, 4), gemm_smem>>>(x, W, bias, out);
    k_clean<<<EE / 256, 256>>>();
}

// round 13
// speedup vs baseline: 1.3797x; 1.0253x over previous
#include <cuda_runtime.h>
#include <cuda_fp16.h>
#include <math.h>

#define NN 8192
#define EE 262144
#define CC 64
#define NMASK (NN - 1)
#define ELLW 96
#define HBITS 20
#define HSIZE (1 << HBITS)
#define HMASK (HSIZE - 1)
#define WP 68   // padded W column stride (16B aligned, conflict-free LDS.128)

typedef unsigned long long u64;

// ---- static device scratch (zero-initialized at module load) ----
__device__ u64     g_hash[HSIZE];          // 8 MB open-addressed LWW table (L2-resident)
__device__ int     g_slotrec[EE];          // slot touched by each edge (for clean)
__device__ int     g_rowcnt[NN];
__device__ float   g_deg[NN];              // accumulated edge weight (identity added in prep)
__device__ float   g_dinv[NN];
__device__ u64     g_ell[NN * ELLW];       // packed (w_bits<<32 | col); row stride 768B
__device__ __half2 g_zh[NN * 32];          // fp16: dinv * x      (gathered operand)
__device__ float   g_tx1[NN * CC];
__device__ __half2 g_zth[NN * 32];         // fp16: dinv * tx1    (gathered operand)
__device__ float   g_tx2[NN * CC];

__device__ __forceinline__ void add_entry(int r, int c, float w) {
    int pos = atomicAdd(&g_rowcnt[r], 1);
    if (pos < ELLW) {
        u64 pk = ((u64)__float_as_uint(w) << 32) | (u64)(unsigned)c;
        g_ell[r * ELLW + pos] = pk;
    }
    atomicAdd(&g_deg[r], w);
}

// ---- K1: single-pass dedup + ELL build via L2-resident hash ----
__global__ void k_build(const int* __restrict__ ei, const float* __restrict__ ew,
                        const float* __restrict__ adaptive) {
    int e = blockIdx.x * blockDim.x + threadIdx.x;
    if (e >= EE) return;
    float sig = 1.0f / (1.0f + expf(-adaptive[0]));
    int r = ei[e] & NMASK;
    int c = ei[EE + e] & NMASK;
    unsigned key = (unsigned)(r * NN + c);          // < 2^26
    u64 desired = ((u64)(key + 1) << 32) | (u64)(unsigned)(e + 1);
    unsigned slot = (key * 2654435761u) >> (32 - HBITS);
    float aw = ew[e] * sig;
    while (true) {
        u64 old = atomicCAS(&g_hash[slot], 0ULL, desired);
        if (old == 0ULL) {
            add_entry(r, c, aw);
            g_slotrec[e] = (int)slot;
            break;
        }
        if ((unsigned)(old >> 32) == key + 1) {
            if ((unsigned)old < (unsigned)(e + 1)) {
                u64 prev = atomicMax(&g_hash[slot], desired);
                if ((unsigned)prev < (unsigned)(e + 1)) {
                    int eprev = (int)(unsigned)prev - 1;
                    add_entry(r, c, aw);
                    add_entry(r, c, -(ew[eprev] * sig));
                }
            }
            g_slotrec[e] = (int)slot;
            break;
        }
        slot = (slot + 1) & HMASK;
    }
}

// ---- K2: dinv = (1+deg)^-1/2 ; zh = half2(dinv*x) ----
__global__ void k_prep(const float* __restrict__ x) {
    int i = blockIdx.x * blockDim.x + threadIdx.x;
    if (i >= NN * 32) return;
    int row = i >> 5;
    float di = rsqrtf(1.0f + g_deg[row]);
    float2 v = ((const float2*)x)[i];
    g_zh[i] = __floats2half2_rn(di * v.x, di * v.y);
    if ((i & 31) == 0) g_dinv[row] = di;
}

// ---- shared SpMM row body: MLP-8 gather of half2 (4B/lane = 4 sectors/row) ----
__device__ __forceinline__ float2 gather_row(const __half2* __restrict__ zh,
                                             int row, int t) {
    float2 acc = __half22float2(zh[row * 32 + t]);   // identity term
    int cnt = g_rowcnt[row]; if (cnt > ELLW) cnt = ELLW;
    const ulonglong2* ell2 = (const ulonglong2*)&g_ell[row * ELLW];
    int k = 0;
    for (; k + 8 <= cnt; k += 8) {
        ulonglong2 q0 = __ldg(&ell2[(k >> 1)]);
        ulonglong2 q1 = __ldg(&ell2[(k >> 1) + 1]);
        ulonglong2 q2 = __ldg(&ell2[(k >> 1) + 2]);
        ulonglong2 q3 = __ldg(&ell2[(k >> 1) + 3]);
        __half2 h0 = zh[(int)(q0.x & 0xffffffffu) * 32 + t];
        __half2 h1 = zh[(int)(q0.y & 0xffffffffu) * 32 + t];
        __half2 h2 = zh[(int)(q1.x & 0xffffffffu) * 32 + t];
        __half2 h3 = zh[(int)(q1.y & 0xffffffffu) * 32 + t];
        __half2 h4 = zh[(int)(q2.x & 0xffffffffu) * 32 + t];
        __half2 h5 = zh[(int)(q2.y & 0xffffffffu) * 32 + t];
        __half2 h6 = zh[(int)(q3.x & 0xffffffffu) * 32 + t];
        __half2 h7 = zh[(int)(q3.y & 0xffffffffu) * 32 + t];
        float w0 = __uint_as_float((unsigned)(q0.x >> 32));
        float w1 = __uint_as_float((unsigned)(q0.y >> 32));
        float w2 = __uint_as_float((unsigned)(q1.x >> 32));
        float w3 = __uint_as_float((unsigned)(q1.y >> 32));
        float w4 = __uint_as_float((unsigned)(q2.x >> 32));
        float w5 = __uint_as_float((unsigned)(q2.y >> 32));
        float w6 = __uint_as_float((unsigned)(q3.x >> 32));
        float w7 = __uint_as_float((unsigned)(q3.y >> 32));
        float2 c0 = __half22float2(h0);
        float2 c1 = __half22float2(h1);
        float2 c2 = __half22float2(h2);
        float2 c3 = __half22float2(h3);
        float2 c4 = __half22float2(h4);
        float2 c5 = __half22float2(h5);
        float2 c6 = __half22float2(h6);
        float2 c7 = __half22float2(h7);
        acc.x += w0 * c0.x; acc.y += w0 * c0.y;
        acc.x += w1 * c1.x; acc.y += w1 * c1.y;
        acc.x += w2 * c2.x; acc.y += w2 * c2.y;
        acc.x += w3 * c3.x; acc.y += w3 * c3.y;
        acc.x += w4 * c4.x; acc.y += w4 * c4.y;
        acc.x += w5 * c5.x; acc.y += w5 * c5.y;
        acc.x += w6 * c6.x; acc.y += w6 * c6.y;
        acc.x += w7 * c7.x; acc.y += w7 * c7.y;
    }
    for (; k < cnt; k++) {
        u64 pk = __ldg(&g_ell[row * ELLW + k]);
        float2 zc = __half22float2(zh[(int)(pk & 0xffffffffu) * 32 + t]);
        float w = __uint_as_float((unsigned)(pk >> 32));
        acc.x += w * zc.x; acc.y += w * zc.y;
    }
    return acc;
}

// ---- K3: tx1 = L @ x ; zth = half2(dinv*tx1) ----
__global__ void __launch_bounds__(256) k_spmm1(const float* __restrict__ x) {
    int row = blockIdx.x * 8 + threadIdx.y;
    int t = threadIdx.x;
    float2 acc = gather_row(g_zh, row, t);
    float di = g_dinv[row];
    float2 xr = ((const float2*)x)[row * 32 + t];
    float2 y; y.x = xr.x - di * acc.x; y.y = xr.y - di * acc.y;
    ((float2*)g_tx1)[row * 32 + t] = y;
    g_zth[row * 32 + t] = __floats2half2_rn(di * y.x, di * y.y);
}

// ---- K4: tx2 = 2*(L @ tx1) - x ----
__global__ void __launch_bounds__(256) k_spmm2(const float* __restrict__ x) {
    int row = blockIdx.x * 8 + threadIdx.y;
    int t = threadIdx.x;
    float2 acc = gather_row(g_zth, row, t);
    float di = g_dinv[row];
    float2 x1 = ((const float2*)g_tx1)[row * 32 + t];
    float2 x0 = ((const float2*)x)[row * 32 + t];
    float2 y;
    y.x = 2.0f * (x1.x - di * acc.x) - x0.x;
    y.y = 2.0f * (x1.y - di * acc.y) - x0.y;
    ((float2*)g_tx2)[row * 32 + t] = y;
}

// ---- K5: out = x@W0 + tx1@W1 + tx2@W2 + bias ----
extern __shared__ float s_dyn[];
__global__ void __launch_bounds__(256) k_gemm(const float* __restrict__ x,
                                              const float* __restrict__ W,
                                              const float* __restrict__ bias,
                                              float* __restrict__ out) {
    float* sWt = s_dyn;                     // 3 * 64 * WP floats ~= 51 KB
    int o = threadIdx.x;                    // 0..63 out channel
    int ty = threadIdx.y;                   // 0..3
    int tid = ty * 64 + o;
    for (int i = tid; i < 3 * CC * CC; i += 256) {
        int m = i >> 12;
        int rem = i & 4095;
        int c = rem >> 6, oo = rem & 63;
        sWt[(m * CC + oo) * WP + c] = W[i];
    }
    __syncthreads();

    const float* w0 = &sWt[(0 * CC + o) * WP];
    const float* w1 = &sWt[(1 * CC + o) * WP];
    const float* w2 = &sWt[(2 * CC + o) * WP];
    int rbase = blockIdx.x * 32;
    float b = bias[o];
#pragma unroll
    for (int j = 0; j < 8; j++) {
        int row = rbase + j * 4 + ty;
        const float4* x4  = (const float4*)(x + row * CC);
        const float4* t14 = (const float4*)(g_tx1 + row * CC);
        const float4* t24 = (const float4*)(g_tx2 + row * CC);
        float a = b;
#pragma unroll
        for (int c4 = 0; c4 < 16; c4++) {
            float4 v0 = __ldg(&x4[c4]);
            float4 v1 = __ldg(&t14[c4]);
            float4 v2 = __ldg(&t24[c4]);
            float4 u0 = *(const float4*)&w0[c4 * 4];
            float4 u1 = *(const float4*)&w1[c4 * 4];
            float4 u2 = *(const float4*)&w2[c4 * 4];
            a += v0.x * u0.x + v0.y * u0.y + v0.z * u0.z + v0.w * u0.w;
            a += v1.x * u1.x + v1.y * u1.y + v1.z * u1.z + v1.w * u1.w;
            a += v2.x * u2.x + v2.y * u2.y + v2.z * u2.z + v2.w * u2.w;
        }
        out[row * CC + o] = a;
    }
}

// ---- K6: clean touched hash slots + per-row counters for next replay ----
__global__ void k_clean() {
    int i = blockIdx.x * blockDim.x + threadIdx.x;
    if (i < NN) { g_deg[i] = 0.0f; g_rowcnt[i] = 0; }
    if (i < EE) g_hash[g_slotrec[i]] = 0ULL;
}

extern "C" void kernel_launch(void* const* d_in, const int* in_sizes, int n_in,
                              void* d_out, int out_size) {
    const float* x        = (const float*)d_in[0];
    const int*   ei       = (const int*)d_in[1];
    const float* ew       = (const float*)d_in[2];
    const float* W        = (const float*)d_in[3];
    const float* adaptive = (const float*)d_in[4];
    const float* bias     = (const float*)d_in[5];
    float* out = (float*)d_out;

    const int gemm_smem = 3 * CC * WP * sizeof(float);   // ~51 KB
    cudaFuncSetAttribute(k_gemm, cudaFuncAttributeMaxDynamicSharedMemorySize, gemm_smem);

    k_build<<<EE / 256, 256>>>(ei, ew, adaptive);
    k_prep<<<(NN * 32) / 256, 256>>>(x);
    k_spmm1<<<NN / 8, dim3(32, 8)>>>(x);
    k_spmm2<<<NN / 8, dim3(32, 8)>>>(x);
    k_gemm<<<NN / 32, dim3(64, 4), gemm_smem>>>(x, W, bias, out);
    k_clean<<<EE / 256, 256>>>();
}

// round 15
// speedup vs baseline: 1.4339x; 1.0393x over previous
#include <cuda_runtime.h>
#include <cuda_fp16.h>
#include <math.h>

#define NN 8192
#define EE 262144
#define CC 64
#define NMASK (NN - 1)
#define ELLW 96
#define HBITS 20
#define HSIZE (1 << HBITS)
#define HMASK (HSIZE - 1)
#define WP 68   // padded W column stride (16B aligned, conflict-free LDS.128)

typedef unsigned long long u64;

// ---- static device scratch (zero-initialized at module load) ----
__device__ u64     g_hash[HSIZE];          // 8 MB open-addressed LWW table (L2-resident)
__device__ int     g_rowcnt[NN];
__device__ float   g_dinv[NN];
__device__ u64     g_ell[NN * ELLW];       // packed (w_bits<<32 | col); row stride 768B
__device__ __half2 g_zh[NN * 32];          // fp16: dinv * x      (gathered operand)
__device__ float   g_tx1[NN * CC];
__device__ __half2 g_zth[NN * 32];         // fp16: dinv * tx1    (gathered operand)
__device__ float   g_tx2[NN * CC];

__device__ __forceinline__ void add_entry(int r, int c, float w) {
    int pos = atomicAdd(&g_rowcnt[r], 1);
    if (pos < ELLW) {
        u64 pk = ((u64)__float_as_uint(w) << 32) | (u64)(unsigned)c;
        g_ell[r * ELLW + pos] = pk;
    }
}

// ---- K1: single-pass dedup + ELL build via L2-resident hash ----
// Net ELL row sum per (r,c) == final winner's weight (displacements subtract
// their predecessor's weight). deg is recovered later as the ELL row sum.
__global__ void k_build(const int* __restrict__ ei, const float* __restrict__ ew,
                        const float* __restrict__ adaptive) {
    int e = blockIdx.x * blockDim.x + threadIdx.x;
    if (e >= EE) return;
    float sig = 1.0f / (1.0f + expf(-adaptive[0]));
    int r = ei[e] & NMASK;
    int c = ei[EE + e] & NMASK;
    unsigned key = (unsigned)(r * NN + c);          // < 2^26
    u64 desired = ((u64)(key + 1) << 32) | (u64)(unsigned)(e + 1);
    unsigned slot = (key * 2654435761u) >> (32 - HBITS);
    float aw = ew[e] * sig;
    while (true) {
        u64 old = atomicCAS(&g_hash[slot], 0ULL, desired);
        if (old == 0ULL) {
            add_entry(r, c, aw);
            break;
        }
        if ((unsigned)(old >> 32) == key + 1) {
            if ((unsigned)old < (unsigned)(e + 1)) {
                u64 prev = atomicMax(&g_hash[slot], desired);
                if ((unsigned)prev < (unsigned)(e + 1)) {
                    int eprev = (int)(unsigned)prev - 1;
                    add_entry(r, c, aw);
                    add_entry(r, c, -(ew[eprev] * sig));
                }
            }
            break;
        }
        slot = (slot + 1) & HMASK;
    }
}

// ---- K2: warp-per-row: deg = sum(ELL row w) ; dinv ; zh = half2(dinv*x) ----
__global__ void __launch_bounds__(256) k_prep(const float* __restrict__ x) {
    int row = blockIdx.x * 8 + threadIdx.y;
    int t = threadIdx.x;
    int cnt = g_rowcnt[row]; if (cnt > ELLW) cnt = ELLW;
    float s = 0.0f;
    for (int k = t; k < cnt; k += 32)
        s += __uint_as_float((unsigned)(g_ell[row * ELLW + k] >> 32));
#pragma unroll
    for (int off = 16; off > 0; off >>= 1)
        s += __shfl_xor_sync(0xffffffffu, s, off);
    float di = rsqrtf(1.0f + s);
    if (t == 0) g_dinv[row] = di;
    float2 v = ((const float2*)x)[row * 32 + t];
    g_zh[row * 32 + t] = __floats2half2_rn(di * v.x, di * v.y);
}

// ---- shared SpMM row body: MLP-8 gather of half2 ----
__device__ __forceinline__ float2 gather_row(const __half2* __restrict__ zh,
                                             int row, int t) {
    float2 acc = __half22float2(zh[row * 32 + t]);   // identity term
    int cnt = g_rowcnt[row]; if (cnt > ELLW) cnt = ELLW;
    const ulonglong2* ell2 = (const ulonglong2*)&g_ell[row * ELLW];
    int k = 0;
    for (; k + 8 <= cnt; k += 8) {
        ulonglong2 q0 = __ldg(&ell2[(k >> 1)]);
        ulonglong2 q1 = __ldg(&ell2[(k >> 1) + 1]);
        ulonglong2 q2 = __ldg(&ell2[(k >> 1) + 2]);
        ulonglong2 q3 = __ldg(&ell2[(k >> 1) + 3]);
        __half2 h0 = zh[(int)(q0.x & 0xffffffffu) * 32 + t];
        __half2 h1 = zh[(int)(q0.y & 0xffffffffu) * 32 + t];
        __half2 h2 = zh[(int)(q1.x & 0xffffffffu) * 32 + t];
        __half2 h3 = zh[(int)(q1.y & 0xffffffffu) * 32 + t];
        __half2 h4 = zh[(int)(q2.x & 0xffffffffu) * 32 + t];
        __half2 h5 = zh[(int)(q2.y & 0xffffffffu) * 32 + t];
        __half2 h6 = zh[(int)(q3.x & 0xffffffffu) * 32 + t];
        __half2 h7 = zh[(int)(q3.y & 0xffffffffu) * 32 + t];
        float w0 = __uint_as_float((unsigned)(q0.x >> 32));
        float w1 = __uint_as_float((unsigned)(q0.y >> 32));
        float w2 = __uint_as_float((unsigned)(q1.x >> 32));
        float w3 = __uint_as_float((unsigned)(q1.y >> 32));
        float w4 = __uint_as_float((unsigned)(q2.x >> 32));
        float w5 = __uint_as_float((unsigned)(q2.y >> 32));
        float w6 = __uint_as_float((unsigned)(q3.x >> 32));
        float w7 = __uint_as_float((unsigned)(q3.y >> 32));
        float2 c0 = __half22float2(h0);
        float2 c1 = __half22float2(h1);
        float2 c2 = __half22float2(h2);
        float2 c3 = __half22float2(h3);
        float2 c4 = __half22float2(h4);
        float2 c5 = __half22float2(h5);
        float2 c6 = __half22float2(h6);
        float2 c7 = __half22float2(h7);
        acc.x += w0 * c0.x; acc.y += w0 * c0.y;
        acc.x += w1 * c1.x; acc.y += w1 * c1.y;
        acc.x += w2 * c2.x; acc.y += w2 * c2.y;
        acc.x += w3 * c3.x; acc.y += w3 * c3.y;
        acc.x += w4 * c4.x; acc.y += w4 * c4.y;
        acc.x += w5 * c5.x; acc.y += w5 * c5.y;
        acc.x += w6 * c6.x; acc.y += w6 * c6.y;
        acc.x += w7 * c7.x; acc.y += w7 * c7.y;
    }
    for (; k < cnt; k++) {
        u64 pk = __ldg(&g_ell[row * ELLW + k]);
        float2 zc = __half22float2(zh[(int)(pk & 0xffffffffu) * 32 + t]);
        float w = __uint_as_float((unsigned)(pk >> 32));
        acc.x += w * zc.x; acc.y += w * zc.y;
    }
    return acc;
}

// ---- K3: tx1 = L @ x ; zth = half2(dinv*tx1) ----
__global__ void __launch_bounds__(256) k_spmm1(const float* __restrict__ x) {
    int row = blockIdx.x * 8 + threadIdx.y;
    int t = threadIdx.x;
    float2 acc = gather_row(g_zh, row, t);
    float di = g_dinv[row];
    float2 xr = ((const float2*)x)[row * 32 + t];
    float2 y; y.x = xr.x - di * acc.x; y.y = xr.y - di * acc.y;
    ((float2*)g_tx1)[row * 32 + t] = y;
    g_zth[row * 32 + t] = __floats2half2_rn(di * y.x, di * y.y);
}

// ---- K4: tx2 = 2*(L @ tx1) - x ----
__global__ void __launch_bounds__(256) k_spmm2(const float* __restrict__ x) {
    int row = blockIdx.x * 8 + threadIdx.y;
    int t = threadIdx.x;
    float2 acc = gather_row(g_zth, row, t);
    float di = g_dinv[row];
    float2 x1 = ((const float2*)g_tx1)[row * 32 + t];
    float2 x0 = ((const float2*)x)[row * 32 + t];
    float2 y;
    y.x = 2.0f * (x1.x - di * acc.x) - x0.x;
    y.y = 2.0f * (x1.y - di * acc.y) - x0.y;
    ((float2*)g_tx2)[row * 32 + t] = y;
}

// ---- K5: out = x@W0 + tx1@W1 + tx2@W2 + bias ----
extern __shared__ float s_dyn[];
__global__ void __launch_bounds__(256) k_gemm(const float* __restrict__ x,
                                              const float* __restrict__ W,
                                              const float* __restrict__ bias,
                                              float* __restrict__ out) {
    float* sWt = s_dyn;                     // 3 * 64 * WP floats ~= 51 KB
    int o = threadIdx.x;                    // 0..63 out channel
    int ty = threadIdx.y;                   // 0..3
    int tid = ty * 64 + o;
    for (int i = tid; i < 3 * CC * CC; i += 256) {
        int m = i >> 12;
        int rem = i & 4095;
        int c = rem >> 6, oo = rem & 63;
        sWt[(m * CC + oo) * WP + c] = W[i];
    }
    __syncthreads();

    const float* w0 = &sWt[(0 * CC + o) * WP];
    const float* w1 = &sWt[(1 * CC + o) * WP];
    const float* w2 = &sWt[(2 * CC + o) * WP];
    int rbase = blockIdx.x * 32;
    float b = bias[o];
#pragma unroll
    for (int j = 0; j < 8; j++) {
        int row = rbase + j * 4 + ty;
        const float4* x4  = (const float4*)(x + row * CC);
        const float4* t14 = (const float4*)(g_tx1 + row * CC);
        const float4* t24 = (const float4*)(g_tx2 + row * CC);
        float a = b;
#pragma unroll
        for (int c4 = 0; c4 < 16; c4++) {
            float4 v0 = __ldg(&x4[c4]);
            float4 v1 = __ldg(&t14[c4]);
            float4 v2 = __ldg(&t24[c4]);
            float4 u0 = *(const float4*)&w0[c4 * 4];
            float4 u1 = *(const float4*)&w1[c4 * 4];
            float4 u2 = *(const float4*)&w2[c4 * 4];
            a += v0.x * u0.x + v0.y * u0.y + v0.z * u0.z + v0.w * u0.w;
            a += v1.x * u1.x + v1.y * u1.y + v1.z * u1.z + v1.w * u1.w;
            a += v2.x * u2.x + v2.y * u2.y + v2.z * u2.z + v2.w * u2.w;
        }
        out[row * CC + o] = a;
    }
}

// ---- K6: wholesale hash memset (coalesced) + counter reset ----
__global__ void k_clean() {
    int i = blockIdx.x * blockDim.x + threadIdx.x;    // 524288 threads
    ((ulonglong2*)g_hash)[i] = make_ulonglong2(0ULL, 0ULL);
    if (i < NN) g_rowcnt[i] = 0;
}

extern "C" void kernel_launch(void* const* d_in, const int* in_sizes, int n_in,
                              void* d_out, int out_size) {
    const float* x        = (const float*)d_in[0];
    const int*   ei       = (const int*)d_in[1];
    const float* ew       = (const float*)d_in[2];
    const float* W        = (const float*)d_in[3];
    const float* adaptive = (const float*)d_in[4];
    const float* bias     = (const float*)d_in[5];
    float* out = (float*)d_out;

    const int gemm_smem = 3 * CC * WP * sizeof(float);   // ~51 KB
    cudaFuncSetAttribute(k_gemm, cudaFuncAttributeMaxDynamicSharedMemorySize, gemm_smem);

    k_build<<<EE / 256, 256>>>(ei, ew, adaptive);
    k_prep<<<NN / 8, dim3(32, 8)>>>(x);
    k_spmm1<<<NN / 8, dim3(32, 8)>>>(x);
    k_spmm2<<<NN / 8, dim3(32, 8)>>>(x);
    k_gemm<<<NN / 32, dim3(64, 4), gemm_smem>>>(x, W, bias, out);
    k_clean<<<(HSIZE / 2) / 256, 256>>>();
}